// round 17
// baseline (speedup 1.0000x reference)
#include <cuda_runtime.h>

// Problem constants (fixed by the reference)
#define HS_N    4096
#define HS_P    10
#define HS_D    17
#define HS_PD   (HS_P * HS_D)   // 170 dot products per sample
#define HS_DIM  300             // embedding dim (75 float4)
#define HS_VEC4 (HS_DIM / 4)    // 75

__device__ __forceinline__ float dot4(float4 a, float4 b) {
    return a.x * b.x + a.y * b.y + a.z * b.z + a.w * b.w;
}

__device__ __forceinline__ float4 ldg_pol(const float4* p, unsigned long long pol) {
    float4 v;
    asm("ld.global.nc.L2::cache_hint.v4.f32 {%0,%1,%2,%3}, [%4], %5;"
        : "=f"(v.x), "=f"(v.y), "=f"(v.z), "=f"(v.w)
        : "l"(p), "l"(pol));
    return v;
}

__device__ __forceinline__ void prefetch_l2(const void* p) {
    asm volatile("prefetch.global.L2 [%0];" :: "l"(p));
}

__global__ __launch_bounds__(256, 8)   // pin the 32-reg/8-block point
void skip_gram_hs_kernel(const int*   __restrict__ word_idx,   // [N]
                         const int*   __restrict__ paths,      // [N, P, D]
                         const int*   __restrict__ labels,     // [N, P, D]
                         const float* __restrict__ emb1,       // [VOCAB, DIM]
                         const float* __restrict__ emb2,       // [VOCAB-1, DIM]
                         float*       __restrict__ out,        // [N, P, D]
                         float*       __restrict__ target)     // [N, P, D]
{
    __shared__ int s_idx[HS_PD];
    __shared__ int s_lab[HS_PD];

    const int n    = blockIdx.x;
    const int tid  = threadIdx.x;
    const int warp = tid >> 5;
    const int lane = tid & 31;
    const bool tail = (lane < HS_VEC4 - 64);   // lanes 0..10 own float4 #64..74

    unsigned long long pol;
    asm("createpolicy.fractional.L2::evict_last.b64 %0, 0.9;" : "=l"(pol));

    const int base = n * HS_PD;

    // Stage indices+labels (streaming: read-once data).
    if (tid < HS_PD) {
        s_idx[tid] = __ldcs(paths + base + tid);
        s_lab[tid] = __ldcs(labels + base + tid);
    }

    // proj = emb1[word_idx[n]] in registers per lane (overlaps the staging).
    const int w = __ldg(word_idx + n);
    const float4* __restrict__ prow =
        reinterpret_cast<const float4*>(emb1 + (size_t)w * HS_DIM);
    const float4 p0 = __ldg(prow + lane);
    const float4 p1 = __ldg(prow + lane + 32);
    const float4 p2 = tail ? __ldg(prow + lane + 64) : make_float4(0.f, 0.f, 0.f, 0.f);

    __syncthreads();

    // Prologue: prime pairs 0 and 1 (k=warp..warp+24) into L2 so the first
    // two iterations aren't cold. 11 lines x 2 rows per pair, lanes 0..21.
    if (lane < 22) {
        const int ia = (lane & 1) ? s_idx[warp + 8] : s_idx[warp];
        prefetch_l2(reinterpret_cast<const char*>(emb2 + (size_t)ia * HS_DIM)
                    + (lane >> 1) * 128);
        const int ib = (lane & 1) ? s_idx[warp + 24] : s_idx[warp + 16];
        prefetch_l2(reinterpret_cast<const char*>(emb2 + (size_t)ib * HS_DIM)
                    + (lane >> 1) * 128);
    }

    const float4 z = make_float4(0.f, 0.f, 0.f, 0.f);

    // Distance-2 L2 prefetch: pair k+32's lines get >=2 iterations (~1000+
    // cyc) to finish the DRAM hop before their loads issue.
    int k = warp;
    for (; k + 8 < HS_PD; k += 16) {
        {
            const int kn  = (k + 32 < HS_PD) ? k + 32 : k;   // clamp: dup, harmless
            const int kn8 = (kn + 8 < HS_PD) ? kn + 8 : kn;
            if (lane < 22) {
                const int idn = (lane & 1) ? s_idx[kn8] : s_idx[kn];
                prefetch_l2(reinterpret_cast<const char*>(emb2 + (size_t)idn * HS_DIM)
                            + (lane >> 1) * 128);
            }
        }

        const int idx0 = s_idx[k];          // LDS broadcast
        const int idx1 = s_idx[k + 8];
        const float4* __restrict__ r0 =
            reinterpret_cast<const float4*>(emb2 + (size_t)idx0 * HS_DIM);
        const float4* __restrict__ r1 =
            reinterpret_cast<const float4*>(emb2 + (size_t)idx1 * HS_DIM);

        // Issue all 6 wide loads before consuming.
        float4 a0 = ldg_pol(r0 + lane, pol);
        float4 a1 = ldg_pol(r0 + lane + 32, pol);
        float4 b0 = ldg_pol(r1 + lane, pol);
        float4 b1 = ldg_pol(r1 + lane + 32, pol);
        float4 a2 = z, b2 = z;
        if (tail) { a2 = ldg_pol(r0 + lane + 64, pol); b2 = ldg_pol(r1 + lane + 64, pol); }

        float s0 = dot4(a0, p0) + dot4(a1, p1) + dot4(a2, p2);
        float s1 = dot4(b0, p0) + dot4(b1, p1) + dot4(b2, p2);

        // Two independent butterfly chains (tree identical to R5..R15 ->
        // bit-identical outputs).
        #pragma unroll
        for (int off = 16; off > 0; off >>= 1) {
            s0 += __shfl_xor_sync(0xffffffffu, s0, off);
            s1 += __shfl_xor_sync(0xffffffffu, s1, off);
        }

        if (lane == 0) {
            const float o0 = 1.0f / (1.0f + expf(-s0));
            const float o1 = 1.0f / (1.0f + expf(-s1));
            // Threshold the f32 sigmoid VALUE (matches reference rounding at 0.5).
            const int m0 = (o0 >= 0.5f) ? 1 : 0;
            const int m1 = (o1 >= 0.5f) ? 1 : 0;
            const int l0 = s_lab[k];
            const int l1 = s_lab[k + 8];
            __stcs(out + base + k,        o0);
            __stcs(out + base + k + 8,    o1);
            __stcs(target + base + k,     (m0 == l0) ? 1.0f : 0.0f);
            __stcs(target + base + k + 8, (m1 == l1) ? 1.0f : 0.0f);
        }
    }

    // Remainder (at most one k per warp)
    if (k < HS_PD) {
        const int idx = s_idx[k];
        const float4* __restrict__ row =
            reinterpret_cast<const float4*>(emb2 + (size_t)idx * HS_DIM);

        float4 a0 = ldg_pol(row + lane, pol);
        float4 a1 = ldg_pol(row + lane + 32, pol);
        float4 a2 = z;
        if (tail) a2 = ldg_pol(row + lane + 64, pol);

        float s = dot4(a0, p0) + dot4(a1, p1) + dot4(a2, p2);

        #pragma unroll
        for (int off = 16; off > 0; off >>= 1)
            s += __shfl_xor_sync(0xffffffffu, s, off);

        if (lane == 0) {
            const float o = 1.0f / (1.0f + expf(-s));
            const int m = (o >= 0.5f) ? 1 : 0;
            const int l = s_lab[k];
            __stcs(out + base + k,    o);
            __stcs(target + base + k, (m == l) ? 1.0f : 0.0f);
        }
    }
}

extern "C" void kernel_launch(void* const* d_in, const int* in_sizes, int n_in,
                              void* d_out, int out_size)
{
    // metadata order: word_idx, paths, labels, emb1, emb2
    const int*   word_idx = (const int*)  d_in[0];
    const int*   paths    = (const int*)  d_in[1];
    const int*   labels   = (const int*)  d_in[2];
    const float* emb1     = (const float*)d_in[3];
    const float* emb2     = (const float*)d_in[4];

    float* out    = (float*)d_out;                        // first N*P*D: sigmoid
    float* target = (float*)d_out + (size_t)HS_N * HS_PD; // second N*P*D: target

    skip_gram_hs_kernel<<<HS_N, 256>>>(word_idx, paths, labels, emb1, emb2,
                                       out, target);
}